// round 1
// baseline (speedup 1.0000x reference)
#include <cuda_runtime.h>

// PathwayPredictor: fused GNN (embed -> 2x [relu(XW+b); A@H] -> pool -> head)
// One block per molecule. fp32 with packed f32x2 FFMA.
//
// Key trick: final adjacency matmul + sum-pool collapse:
//   sum_n (A@H2)[n,:] = sum_m colsum(A)[m] * H2[m,:]

#define ULL unsigned long long

__device__ __forceinline__ ULL pack2(float v) {
    ULL r; asm("mov.b64 %0, {%1, %1};" : "=l"(r) : "f"(v)); return r;
}
__device__ __forceinline__ void unpack2(ULL v, float& lo, float& hi) {
    asm("mov.b64 {%0, %1}, %2;" : "=f"(lo), "=f"(hi) : "l"(v));
}
__device__ __forceinline__ void fma2(ULL& d, ULL a, ULL b) {
    asm("fma.rn.f32x2 %0, %1, %2, %0;" : "+l"(d) : "l"(a), "l"(b));
}

// C[n][c] += sum_k Xt[k][n] * W[k][c], n-pairs packed in f32x2.
// Xt: K-major, stride 66 floats (even -> 8B-aligned f32x2 loads).
// W : row-major, stride WS.
// Thread tile: rows [rg*8, rg*8+8) as 4 f32x2 pairs, cols [cg*5, cg*5+5).
template<int K>
__device__ __forceinline__ void mm_block(const float* __restrict__ Xt,
                                         const float* __restrict__ Wm, int WS,
                                         ULL acc[4][5], int rg, int cg)
{
    const int rb = rg * 8;
    const int cb = cg * 5;
    #pragma unroll 4
    for (int k = 0; k < K; k++) {
        const float* xr = Xt + k * 66 + rb;
        ULL x0 = *(const ULL*)(xr + 0);
        ULL x1 = *(const ULL*)(xr + 2);
        ULL x2 = *(const ULL*)(xr + 4);
        ULL x3 = *(const ULL*)(xr + 6);
        const float* wr = Wm + k * WS + cb;
        #pragma unroll
        for (int j = 0; j < 5; j++) {
            ULL wv = pack2(wr[j]);
            fma2(acc[0][j], x0, wv);
            fma2(acc[1][j], x1, wv);
            fma2(acc[2][j], x2, wv);
            fma2(acc[3][j], x3, wv);
        }
    }
}

__global__ __launch_bounds__(128, 3)
void pathway_kernel(const int* __restrict__ atoms,
                    const float* __restrict__ adj,
                    const float* __restrict__ sel,
                    const float* __restrict__ emb,
                    const float* __restrict__ w1, const float* __restrict__ b1,
                    const float* __restrict__ w2, const float* __restrict__ b2,
                    const float* __restrict__ wp, const float* __restrict__ bp,
                    float* __restrict__ out)
{
    extern __shared__ float sm[];
    float* sAt  = sm;                 // [64][66]  A^T: sAt[m][n] = A[n][m]
    float* sXt  = sAt + 64 * 66;      // [70][66]  K-major first operand
    float* sH   = sXt + 70 * 66;      // [64][70]  row-major H
    float* sW   = sH + 64 * 70;       // [70][70]  row-major weights
    float* csum = sW + 70 * 70;       // [64]      column sums of A
    float* sy   = csum + 64;          // [80]      pooled features + sel_desc

    const int t = threadIdx.x;
    const int b = blockIdx.x;
    const int lane = t & 31, warp = t >> 5;

    // ---- phase 0: load A (transposed), W1, embed-gather X (transposed) ----
    const float* Ab = adj + (size_t)b * 4096;
    #pragma unroll
    for (int i = t; i < 4096; i += 128) {
        int n = i >> 6, m = i & 63;
        sAt[m * 66 + n] = Ab[i];               // coalesced LDG, 2-way STS conflict
    }
    for (int i = t; i < 4900; i += 128) sW[i] = w1[i];
    // warp w handles atom rows n = w, w+4, ... : coalesced embed-row reads
    for (int n = warp; n < 64; n += 4) {
        int a = atoms[b * 64 + n];
        const float* er = emb + (size_t)a * 70;
        sXt[lane * 66 + n]        = er[lane];
        sXt[(lane + 32) * 66 + n] = er[lane + 32];
        if (lane < 6) sXt[(lane + 64) * 66 + n] = er[lane + 64];
    }
    __syncthreads();

    const int rg = t / 14;            // 8 row-groups (8 rows each)
    const int cg = t - rg * 14;       // 14 col-groups (5 cols each)
    ULL acc[4][5];

    // ---- phase 1: H = relu(X @ W1 + b1) ----
    if (t < 112) {
        #pragma unroll
        for (int p = 0; p < 4; p++)
            #pragma unroll
            for (int j = 0; j < 5; j++) acc[p][j] = 0ull;
        mm_block<70>(sXt, sW, 70, acc, rg, cg);
        #pragma unroll
        for (int j = 0; j < 5; j++) {
            float bj = __ldg(&b1[cg * 5 + j]);
            #pragma unroll
            for (int p = 0; p < 4; p++) {
                float lo, hi; unpack2(acc[p][j], lo, hi);
                int r = rg * 8 + 2 * p, c = cg * 5 + j;
                sH[r * 70 + c]       = fmaxf(lo + bj, 0.f);
                sH[(r + 1) * 70 + c] = fmaxf(hi + bj, 0.f);
            }
        }
    }
    __syncthreads();

    // ---- phase 2: X' = A @ H (write transposed), W2 copy, colsum(A) ----
    for (int i = t; i < 4900; i += 128) sW[i] = w2[i];   // sW free (synced)
    if (t < 112) {
        #pragma unroll
        for (int p = 0; p < 4; p++)
            #pragma unroll
            for (int j = 0; j < 5; j++) acc[p][j] = 0ull;
        mm_block<64>(sAt, sH, 70, acc, rg, cg);          // C[n][d] = sum_m At[m][n] H[m][d]
        #pragma unroll
        for (int j = 0; j < 5; j++)
            #pragma unroll
            for (int p = 0; p < 4; p++) {
                int c = cg * 5 + j, r = rg * 8 + 2 * p;
                *(ULL*)&sXt[c * 66 + r] = acc[p][j];     // aligned f32x2 store
            }
    } else {
        // spare threads: colsum[m] = sum_n A[n][m] = sum_n sAt[m][n]
        for (int m = t - 112; m < 64; m += 16) {
            float s = 0.f;
            #pragma unroll 8
            for (int n = 0; n < 64; n++) s += sAt[m * 66 + n];
            csum[m] = s;
        }
    }
    __syncthreads();

    // ---- phase 3: H2 = relu(X' @ W2 + b2) ----
    if (t < 112) {
        #pragma unroll
        for (int p = 0; p < 4; p++)
            #pragma unroll
            for (int j = 0; j < 5; j++) acc[p][j] = 0ull;
        mm_block<70>(sXt, sW, 70, acc, rg, cg);
        #pragma unroll
        for (int j = 0; j < 5; j++) {
            float bj = __ldg(&b2[cg * 5 + j]);
            #pragma unroll
            for (int p = 0; p < 4; p++) {
                float lo, hi; unpack2(acc[p][j], lo, hi);
                int r = rg * 8 + 2 * p, c = cg * 5 + j;
                sH[r * 70 + c]       = fmaxf(lo + bj, 0.f);
                sH[(r + 1) * 70 + c] = fmaxf(hi + bj, 0.f);
            }
        }
    }
    __syncthreads();

    // ---- phase 4: pool  y[d] = sum_m colsum[m] * H2[m][d]; append sel ----
    if (t < 70) {
        float s = 0.f;
        #pragma unroll 8
        for (int m = 0; m < 64; m++) s += csum[m] * sH[m * 70 + t];
        sy[t] = s;
    } else if (t < 77) {
        sy[t] = sel[b * 7 + (t - 70)];
    }
    __syncthreads();

    // ---- phase 5: head  out = y @ wp + bp ----
    if (t < 11) {
        float s = __ldg(&bp[t]);
        #pragma unroll 7
        for (int d = 0; d < 77; d++) s += sy[d] * __ldg(&wp[d * 11 + t]);
        out[b * 11 + t] = s;
    }
}

extern "C" void kernel_launch(void* const* d_in, const int* in_sizes, int n_in,
                              void* d_out, int out_size)
{
    const int*   atoms = (const int*)  d_in[0];
    const float* adj   = (const float*)d_in[1];
    const float* sel   = (const float*)d_in[2];
    const float* emb   = (const float*)d_in[3];
    const float* w1    = (const float*)d_in[4];
    const float* b1    = (const float*)d_in[5];
    const float* w2    = (const float*)d_in[6];
    const float* b2    = (const float*)d_in[7];
    const float* wp    = (const float*)d_in[8];
    const float* bp    = (const float*)d_in[9];
    float* out = (float*)d_out;

    const size_t smem = (size_t)(64*66 + 70*66 + 64*70 + 70*70 + 64 + 80) * sizeof(float);
    cudaFuncSetAttribute(pathway_kernel,
                         cudaFuncAttributeMaxDynamicSharedMemorySize, (int)smem);
    pathway_kernel<<<8192, 128, smem>>>(atoms, adj, sel, emb,
                                        w1, b1, w2, b2, wp, bp, out);
}

// round 2
// speedup vs baseline: 1.0001x; 1.0001x over previous
#include <cuda_runtime.h>

// PathwayPredictor: fused GNN (embed -> 2x [relu(XW+b); A@H] -> pool -> head)
// One block per molecule. fp32 with packed f32x2 FFMA.
//
// Key trick: final adjacency matmul + sum-pool collapse:
//   sum_n (A@H2)[n,:] = sum_m colsum(A)[m] * H2[m,:]

#define ULL unsigned long long

__device__ __forceinline__ ULL pack2(float v) {
    ULL r; asm("mov.b64 %0, {%1, %1};" : "=l"(r) : "f"(v)); return r;
}
__device__ __forceinline__ void unpack2(ULL v, float& lo, float& hi) {
    asm("mov.b64 {%0, %1}, %2;" : "=f"(lo), "=f"(hi) : "l"(v));
}
__device__ __forceinline__ void fma2(ULL& d, ULL a, ULL b) {
    asm("fma.rn.f32x2 %0, %1, %2, %0;" : "+l"(d) : "l"(a), "l"(b));
}

// C[n][c] += sum_k Xt[k][n] * W[k][c], n-pairs packed in f32x2.
// Xt: K-major, stride 66 floats (even -> 8B-aligned f32x2 loads).
// W : row-major, stride WS.
// Thread tile: rows [rg*8, rg*8+8) as 4 f32x2 pairs, cols [cg*5, cg*5+5).
template<int K>
__device__ __forceinline__ void mm_block(const float* __restrict__ Xt,
                                         const float* __restrict__ Wm, int WS,
                                         ULL acc[4][5], int rg, int cg)
{
    const int rb = rg * 8;
    const int cb = cg * 5;
    #pragma unroll 4
    for (int k = 0; k < K; k++) {
        const float* xr = Xt + k * 66 + rb;
        ULL x0 = *(const ULL*)(xr + 0);
        ULL x1 = *(const ULL*)(xr + 2);
        ULL x2 = *(const ULL*)(xr + 4);
        ULL x3 = *(const ULL*)(xr + 6);
        const float* wr = Wm + k * WS + cb;
        #pragma unroll
        for (int j = 0; j < 5; j++) {
            ULL wv = pack2(wr[j]);
            fma2(acc[0][j], x0, wv);
            fma2(acc[1][j], x1, wv);
            fma2(acc[2][j], x2, wv);
            fma2(acc[3][j], x3, wv);
        }
    }
}

__global__ __launch_bounds__(128, 3)
void pathway_kernel(const int* __restrict__ atoms,
                    const float* __restrict__ adj,
                    const float* __restrict__ sel,
                    const float* __restrict__ emb,
                    const float* __restrict__ w1, const float* __restrict__ b1,
                    const float* __restrict__ w2, const float* __restrict__ b2,
                    const float* __restrict__ wp, const float* __restrict__ bp,
                    float* __restrict__ out)
{
    extern __shared__ float sm[];
    float* sAt  = sm;                 // [64][66]  A^T: sAt[m][n] = A[n][m]
    float* sXt  = sAt + 64 * 66;      // [70][66]  K-major first operand
    float* sH   = sXt + 70 * 66;      // [64][70]  row-major H
    float* sW   = sH + 64 * 70;       // [70][70]  row-major weights
    float* csum = sW + 70 * 70;       // [64]      column sums of A
    float* sy   = csum + 64;          // [80]      pooled features + sel_desc

    const int t = threadIdx.x;
    const int b = blockIdx.x;
    const int lane = t & 31, warp = t >> 5;

    // ---- phase 0: load A (transposed), W1, embed-gather X (transposed) ----
    const float* Ab = adj + (size_t)b * 4096;
    #pragma unroll
    for (int i = t; i < 4096; i += 128) {
        int n = i >> 6, m = i & 63;
        sAt[m * 66 + n] = Ab[i];               // coalesced LDG, 2-way STS conflict
    }
    for (int i = t; i < 4900; i += 128) sW[i] = w1[i];
    // warp w handles atom rows n = w, w+4, ... : coalesced embed-row reads
    for (int n = warp; n < 64; n += 4) {
        int a = atoms[b * 64 + n];
        const float* er = emb + (size_t)a * 70;
        sXt[lane * 66 + n]        = er[lane];
        sXt[(lane + 32) * 66 + n] = er[lane + 32];
        if (lane < 6) sXt[(lane + 64) * 66 + n] = er[lane + 64];
    }
    __syncthreads();

    const int rg = t / 14;            // 8 row-groups (8 rows each)
    const int cg = t - rg * 14;       // 14 col-groups (5 cols each)
    ULL acc[4][5];

    // ---- phase 1: H = relu(X @ W1 + b1) ----
    if (t < 112) {
        #pragma unroll
        for (int p = 0; p < 4; p++)
            #pragma unroll
            for (int j = 0; j < 5; j++) acc[p][j] = 0ull;
        mm_block<70>(sXt, sW, 70, acc, rg, cg);
        #pragma unroll
        for (int j = 0; j < 5; j++) {
            float bj = __ldg(&b1[cg * 5 + j]);
            #pragma unroll
            for (int p = 0; p < 4; p++) {
                float lo, hi; unpack2(acc[p][j], lo, hi);
                int r = rg * 8 + 2 * p, c = cg * 5 + j;
                sH[r * 70 + c]       = fmaxf(lo + bj, 0.f);
                sH[(r + 1) * 70 + c] = fmaxf(hi + bj, 0.f);
            }
        }
    }
    __syncthreads();

    // ---- phase 2: X' = A @ H (write transposed), W2 copy, colsum(A) ----
    for (int i = t; i < 4900; i += 128) sW[i] = w2[i];   // sW free (synced)
    if (t < 112) {
        #pragma unroll
        for (int p = 0; p < 4; p++)
            #pragma unroll
            for (int j = 0; j < 5; j++) acc[p][j] = 0ull;
        mm_block<64>(sAt, sH, 70, acc, rg, cg);          // C[n][d] = sum_m At[m][n] H[m][d]
        #pragma unroll
        for (int j = 0; j < 5; j++)
            #pragma unroll
            for (int p = 0; p < 4; p++) {
                int c = cg * 5 + j, r = rg * 8 + 2 * p;
                *(ULL*)&sXt[c * 66 + r] = acc[p][j];     // aligned f32x2 store
            }
    } else {
        // spare threads: colsum[m] = sum_n A[n][m] = sum_n sAt[m][n]
        for (int m = t - 112; m < 64; m += 16) {
            float s = 0.f;
            #pragma unroll 8
            for (int n = 0; n < 64; n++) s += sAt[m * 66 + n];
            csum[m] = s;
        }
    }
    __syncthreads();

    // ---- phase 3: H2 = relu(X' @ W2 + b2) ----
    if (t < 112) {
        #pragma unroll
        for (int p = 0; p < 4; p++)
            #pragma unroll
            for (int j = 0; j < 5; j++) acc[p][j] = 0ull;
        mm_block<70>(sXt, sW, 70, acc, rg, cg);
        #pragma unroll
        for (int j = 0; j < 5; j++) {
            float bj = __ldg(&b2[cg * 5 + j]);
            #pragma unroll
            for (int p = 0; p < 4; p++) {
                float lo, hi; unpack2(acc[p][j], lo, hi);
                int r = rg * 8 + 2 * p, c = cg * 5 + j;
                sH[r * 70 + c]       = fmaxf(lo + bj, 0.f);
                sH[(r + 1) * 70 + c] = fmaxf(hi + bj, 0.f);
            }
        }
    }
    __syncthreads();

    // ---- phase 4: pool  y[d] = sum_m colsum[m] * H2[m][d]; append sel ----
    if (t < 70) {
        float s = 0.f;
        #pragma unroll 8
        for (int m = 0; m < 64; m++) s += csum[m] * sH[m * 70 + t];
        sy[t] = s;
    } else if (t < 77) {
        sy[t] = sel[b * 7 + (t - 70)];
    }
    __syncthreads();

    // ---- phase 5: head  out = y @ wp + bp ----
    if (t < 11) {
        float s = __ldg(&bp[t]);
        #pragma unroll 7
        for (int d = 0; d < 77; d++) s += sy[d] * __ldg(&wp[d * 11 + t]);
        out[b * 11 + t] = s;
    }
}

extern "C" void kernel_launch(void* const* d_in, const int* in_sizes, int n_in,
                              void* d_out, int out_size)
{
    const int*   atoms = (const int*)  d_in[0];
    const float* adj   = (const float*)d_in[1];
    const float* sel   = (const float*)d_in[2];
    const float* emb   = (const float*)d_in[3];
    const float* w1    = (const float*)d_in[4];
    const float* b1    = (const float*)d_in[5];
    const float* w2    = (const float*)d_in[6];
    const float* b2    = (const float*)d_in[7];
    const float* wp    = (const float*)d_in[8];
    const float* bp    = (const float*)d_in[9];
    float* out = (float*)d_out;

    const size_t smem = (size_t)(64*66 + 70*66 + 64*70 + 70*70 + 64 + 80) * sizeof(float);
    cudaFuncSetAttribute(pathway_kernel,
                         cudaFuncAttributeMaxDynamicSharedMemorySize, (int)smem);
    pathway_kernel<<<8192, 128, smem>>>(atoms, adj, sel, emb,
                                        w1, b1, w2, b2, wp, bp, out);
}

// round 4
// speedup vs baseline: 1.1407x; 1.1406x over previous
#include <cuda_runtime.h>
#include <cuda_bf16.h>
#include <cstdint>

// ============================================================================
// PathwayPredictor via warp-level mma.sync (HMMA bf16, sm_80+ PTX — compiles
// for plain sm_103 target). One molecule per CTA, 4 warps, M=64, N=72.
// fp32 operands split into bf16 hi+lo; 3 MMA terms per GEMM (hh+hl+lh).
// Final adjacency matmul + sum-pool collapsed: y = colsum(A) @ H2.
// ============================================================================

#define SXW 44   // X/X2/W row stride in u32 words (88 bf16)
#define SAW 36   // adjacency / H^T row stride in u32 words (72 bf16)

// smem float indices (const block at byte 0)
#define B1I 0      // b1 padded[72]
#define B2I 72     // b2 padded[72]
#define BPI 144    // bp[11] (16 reserved)
#define CSI 160    // csum[64]
#define PLI 224    // pool partials [4][72]
#define WPI 512    // wp[847]
// byte offsets
#define OFF_X 5632     // X hi (64x88 b16 = 11264 B) + X lo  -> 22528   (X2 aliases)
#define OFF_W 28160    // W hi (72x88 = 12672 B) + W lo      -> 25344
#define OFF_H 53504    // H^T hi (72x72 = 10368 B) + lo      -> 20736   (A fp32 staging aliases)
#define OFF_A 74240    // A hi (64x72 = 9216 B) + A lo       -> 18432
#define SMEM_BYTES 92672

#define WTILE 12672    // one [72][88] bf16 weight tile, bytes

__device__ __align__(16) unsigned char g_wt[2][2][WTILE];  // [layer][hi/lo]

// ---------------- helpers ----------------
__device__ __forceinline__ void split2(float v, uint16_t& h, uint16_t& l) {
    __nv_bfloat16 bh = __float2bfloat16(v);
    h = *reinterpret_cast<uint16_t*>(&bh);
    __nv_bfloat16 bl = __float2bfloat16(v - __bfloat162float(bh));
    l = *reinterpret_cast<uint16_t*>(&bl);
}
__device__ __forceinline__ void split2w(float a, float b, uint32_t& hw, uint32_t& lw) {
    uint16_t h0, l0, h1, l1;
    split2(a, h0, l0); split2(b, h1, l1);
    hw = (uint32_t)h0 | ((uint32_t)h1 << 16);
    lw = (uint32_t)l0 | ((uint32_t)l1 << 16);
}
__device__ __forceinline__ uint16_t hi16(float v) {
    __nv_bfloat16 bh = __float2bfloat16(v);
    return *reinterpret_cast<uint16_t*>(&bh);
}

__device__ __forceinline__ void mma16816(float c[4],
    uint32_t a0, uint32_t a1, uint32_t a2, uint32_t a3,
    uint32_t b0, uint32_t b1)
{
    asm volatile(
        "mma.sync.aligned.m16n8k16.row.col.f32.bf16.bf16.f32 "
        "{%0,%1,%2,%3},{%4,%5,%6,%7},{%8,%9},{%0,%1,%2,%3};"
        : "+f"(c[0]), "+f"(c[1]), "+f"(c[2]), "+f"(c[3])
        : "r"(a0), "r"(a1), "r"(a2), "r"(a3), "r"(b0), "r"(b1));
}

// C[m16 x 72] += Asplit[m16 x 16*ksteps] @ Bsplit^T, 3-term bf16 split.
__device__ __forceinline__ void gemm_tile(
    const uint32_t* __restrict__ Ahi, const uint32_t* __restrict__ Alo, int sa,
    const uint32_t* __restrict__ Bhi, const uint32_t* __restrict__ Blo, int sb,
    int mrow, int q, int qp, int ksteps, float C[9][4])
{
    for (int ks = 0; ks < ksteps; ks++) {
        const int kw = ks * 8;                    // k-offset in u32 words
        const int ra = (mrow + q) * sa + kw + qp;
        uint32_t ah0 = Ahi[ra],        ah1 = Ahi[ra + 8 * sa];
        uint32_t ah2 = Ahi[ra + 4],    ah3 = Ahi[ra + 8 * sa + 4];
        uint32_t al0 = Alo[ra],        al1 = Alo[ra + 8 * sa];
        uint32_t al2 = Alo[ra + 4],    al3 = Alo[ra + 8 * sa + 4];
        #pragma unroll
        for (int n = 0; n < 9; n++) {
            const int rb = (n * 8 + q) * sb + kw + qp;
            uint32_t bh0 = Bhi[rb], bh1 = Bhi[rb + 4];
            uint32_t bl0 = Blo[rb], bl1 = Blo[rb + 4];
            mma16816(C[n], ah0, ah1, ah2, ah3, bh0, bh1);
            mma16816(C[n], ah0, ah1, ah2, ah3, bl0, bl1);
            mma16816(C[n], al0, al1, al2, al3, bh0, bh1);
        }
    }
}

// ---------------- weight prep: W^T split tiles [72 n][88 k] hi/lo ----------------
__global__ void prep_w(const float* __restrict__ w1, const float* __restrict__ w2) {
    int idx = blockIdx.x * 128 + threadIdx.x;
    if (idx >= 2 * 72 * 88) return;
    int l = idx / (72 * 88);
    int r = idx % (72 * 88);
    int n = r / 88, k = r % 88;
    const float* w = l ? w2 : w1;
    float v = (n < 70 && k < 70) ? w[k * 70 + n] : 0.f;
    uint16_t h, lo; split2(v, h, lo);
    *(uint16_t*)(g_wt[l][0] + r * 2) = h;
    *(uint16_t*)(g_wt[l][1] + r * 2) = lo;
}

// ---------------- main kernel ----------------
__global__ __launch_bounds__(128)
void pathway_mma(const int* __restrict__ atoms, const float* __restrict__ adj,
                 const float* __restrict__ sel, const float* __restrict__ emb,
                 const float* __restrict__ b1, const float* __restrict__ b2,
                 const float* __restrict__ wp, const float* __restrict__ bp,
                 float* __restrict__ out)
{
    extern __shared__ __align__(16) unsigned char sm[];
    float* smf = (float*)sm;
    const int t = threadIdx.x, lane = t & 31, wid = t >> 5;
    const int bid = blockIdx.x;
    const int q = lane >> 2, qp = lane & 3;   // quad row / quad pos
    const int mrow = wid * 16;                // warp's m-tile base row

    uint32_t* XhiW = (uint32_t*)(sm + OFF_X);       uint32_t* XloW = XhiW + 64 * SXW;
    uint32_t* WhiW = (uint32_t*)(sm + OFF_W);       uint32_t* WloW = WhiW + 72 * SXW;
    uint32_t* HhiW = (uint32_t*)(sm + OFF_H);       uint32_t* HloW = HhiW + 72 * SAW;
    uint32_t* AhiW = (uint32_t*)(sm + OFF_A);       uint32_t* AloW = AhiW + 64 * SAW;
    uint16_t* H16h = (uint16_t*)(sm + OFF_H);       uint16_t* H16l = H16h + 72 * 72;
    float*    Afp  = (float*)(sm + OFF_H);          // staging, aliases H (dead before epi1)

    // ================= phase 0: loads =================
    {   // adjacency fp32 -> staging [64][65]
        const float* Ab = adj + (size_t)bid * 4096;
        #pragma unroll
        for (int i = t; i < 4096; i += 128)
            Afp[(i >> 6) * 65 + (i & 63)] = Ab[i];
    }
    {   // W1 split tiles -> smem (hi+lo contiguous, 25344 B)
        const uint4* gw = (const uint4*)g_wt[0][0];
        uint4* sw = (uint4*)(sm + OFF_W);
        #pragma unroll
        for (int i = t; i < 2 * WTILE / 16; i += 128) sw[i] = gw[i];
    }
    if (t < 72) { smf[B1I + t] = (t < 70) ? b1[t] : 0.f;
                  smf[B2I + t] = (t < 70) ? b2[t] : 0.f; }
    if (t < 11) smf[BPI + t] = bp[t];
    for (int i = t; i < 847; i += 128) smf[WPI + i] = wp[i];

    {   // embed gather -> X hi/lo split (2 threads per atom)
        const int atom = t >> 1, half = t & 1;
        const int a = atoms[(size_t)bid * 64 + atom];
        const float* er = emb + (size_t)a * 70;
        uint32_t* xh = XhiW + atom * SXW;
        uint32_t* xl = XloW + atom * SXW;
        if (half == 0) {
            #pragma unroll
            for (int j = 0; j < 18; j++) {
                uint32_t hw, lw; split2w(er[2 * j], er[2 * j + 1], hw, lw);
                xh[j] = hw; xl[j] = lw;
            }
        } else {
            #pragma unroll
            for (int j = 0; j < 17; j++) {
                uint32_t hw, lw; split2w(er[36 + 2 * j], er[37 + 2 * j], hw, lw);
                xh[18 + j] = hw; xl[18 + j] = lw;
            }
            #pragma unroll
            for (int j = 35; j < 40; j++) { xh[j] = 0; xl[j] = 0; }   // k 70..79 zero
        }
    }
    __syncthreads();

    // colsum + A split
    if (t < 64) {
        float s = 0.f;
        #pragma unroll 8
        for (int n = 0; n < 64; n++) s += Afp[n * 65 + t];
        smf[CSI + t] = s;
    }
    {   // split A: thread handles row t/2, half (t&1)*32
        const int n = t >> 1, mb = (t & 1) * 32;
        const float* ar = Afp + n * 65 + mb;
        uint32_t* ah = AhiW + n * SAW + (mb >> 1);
        uint32_t* al = AloW + n * SAW + (mb >> 1);
        #pragma unroll
        for (int j = 0; j < 16; j++) {
            uint32_t hw, lw; split2w(ar[2 * j], ar[2 * j + 1], hw, lw);
            ah[j] = hw; al[j] = lw;
        }
    }
    __syncthreads();

    float C[9][4];

    // ================= GEMM1: D1 = X @ W1^T  (K=80) =================
    #pragma unroll
    for (int n = 0; n < 9; n++)
        #pragma unroll
        for (int i = 0; i < 4; i++) C[n][i] = 0.f;
    gemm_tile(XhiW, XloW, SXW, WhiW, WloW, SXW, mrow, q, qp, 5, C);

    // epi1: H1 = relu(D1 + b1) -> H^T hi/lo (transposed scatter, b16 stores)
    {
        const int r0 = mrow + q, r1 = r0 + 8;
        #pragma unroll
        for (int n = 0; n < 9; n++) {
            const int d0 = n * 8 + qp * 2;
            float h00 = fmaxf(C[n][0] + smf[B1I + d0], 0.f);
            float h01 = fmaxf(C[n][1] + smf[B1I + d0 + 1], 0.f);
            float h10 = fmaxf(C[n][2] + smf[B1I + d0], 0.f);
            float h11 = fmaxf(C[n][3] + smf[B1I + d0 + 1], 0.f);
            uint16_t hh, hl;
            split2(h00, hh, hl); H16h[d0 * 72 + r0] = hh;       H16l[d0 * 72 + r0] = hl;
            split2(h01, hh, hl); H16h[(d0 + 1) * 72 + r0] = hh; H16l[(d0 + 1) * 72 + r0] = hl;
            split2(h10, hh, hl); H16h[d0 * 72 + r1] = hh;       H16l[d0 * 72 + r1] = hl;
            split2(h11, hh, hl); H16h[(d0 + 1) * 72 + r1] = hh; H16l[(d0 + 1) * 72 + r1] = hl;
        }
    }
    __syncthreads();   // H^T complete; W1 fully consumed

    {   // load W2 split tiles over W1
        const uint4* gw = (const uint4*)g_wt[1][0];
        uint4* sw = (uint4*)(sm + OFF_W);
        #pragma unroll
        for (int i = t; i < 2 * WTILE / 16; i += 128) sw[i] = gw[i];
    }

    // ================= GEMM2: D2 = A @ H1  (K=64) =================
    #pragma unroll
    for (int n = 0; n < 9; n++)
        #pragma unroll
        for (int i = 0; i < 4; i++) C[n][i] = 0.f;
    gemm_tile(AhiW, AloW, SAW, HhiW, HloW, SAW, mrow, q, qp, 4, C);

    // epi2: X2 = D2 -> split -> row-major hi/lo (packed u32 stores), zero k 72..79
    {
        const int r0 = mrow + q, r1 = r0 + 8;
        #pragma unroll
        for (int n = 0; n < 9; n++) {
            const int wofs = n * 4 + qp;         // word index d/2
            uint32_t hw, lw;
            split2w(C[n][0], C[n][1], hw, lw);
            XhiW[r0 * SXW + wofs] = hw; XloW[r0 * SXW + wofs] = lw;
            split2w(C[n][2], C[n][3], hw, lw);
            XhiW[r1 * SXW + wofs] = hw; XloW[r1 * SXW + wofs] = lw;
        }
        XhiW[r0 * SXW + 36 + qp] = 0; XloW[r0 * SXW + 36 + qp] = 0;
        XhiW[r1 * SXW + 36 + qp] = 0; XloW[r1 * SXW + 36 + qp] = 0;
    }
    __syncthreads();   // X2 + W2 ready

    // ================= GEMM3: D3 = X2 @ W2^T  (K=80) =================
    #pragma unroll
    for (int n = 0; n < 9; n++)
        #pragma unroll
        for (int i = 0; i < 4; i++) C[n][i] = 0.f;
    gemm_tile(XhiW, XloW, SXW, WhiW, WloW, SXW, mrow, q, qp, 5, C);

    // epi3: pool y[d] = sum_r csum[r] * relu(D3[r][d] + b2[d])
    {
        const float cs0 = smf[CSI + mrow + q];
        const float cs1 = smf[CSI + mrow + q + 8];
        #pragma unroll
        for (int n = 0; n < 9; n++) {
            #pragma unroll
            for (int j = 0; j < 2; j++) {
                const int d = n * 8 + qp * 2 + j;
                float v = cs0 * fmaxf(C[n][j] + smf[B2I + d], 0.f)
                        + cs1 * fmaxf(C[n][2 + j] + smf[B2I + d], 0.f);
                v += __shfl_xor_sync(0xFFFFFFFFu, v, 4);
                v += __shfl_xor_sync(0xFFFFFFFFu, v, 8);
                v += __shfl_xor_sync(0xFFFFFFFFu, v, 16);
                if (q == 0) smf[PLI + wid * 72 + d] = v;
            }
        }
    }
    __syncthreads();

    // reduce 4 warps -> pool, then head
    if (t < 72) {
        float y = smf[PLI + t] + smf[PLI + 72 + t]
                + smf[PLI + 144 + t] + smf[PLI + 216 + t];
        smf[PLI + t] = y;
    }
    __syncthreads();

    if (t < 11) {
        float s = smf[BPI + t];
        #pragma unroll 7
        for (int d = 0; d < 70; d++)
            s += smf[PLI + d] * smf[WPI + d * 11 + t];
        const float* sv = sel + (size_t)bid * 7;
        #pragma unroll
        for (int e = 0; e < 7; e++)
            s += __ldg(&sv[e]) * smf[WPI + (70 + e) * 11 + t];
        out[(size_t)bid * 11 + t] = s;
    }
}

extern "C" void kernel_launch(void* const* d_in, const int* in_sizes, int n_in,
                              void* d_out, int out_size)
{
    const int*   atoms = (const int*)  d_in[0];
    const float* adj   = (const float*)d_in[1];
    const float* sel   = (const float*)d_in[2];
    const float* emb   = (const float*)d_in[3];
    const float* w1    = (const float*)d_in[4];
    const float* b1    = (const float*)d_in[5];
    const float* w2    = (const float*)d_in[6];
    const float* b2    = (const float*)d_in[7];
    const float* wp    = (const float*)d_in[8];
    const float* bp    = (const float*)d_in[9];
    float* out = (float*)d_out;

    prep_w<<<(2 * 72 * 88 + 127) / 128, 128>>>(w1, w2);

    cudaFuncSetAttribute(pathway_mma,
                         cudaFuncAttributeMaxDynamicSharedMemorySize, SMEM_BYTES);
    pathway_mma<<<8192, 128, SMEM_BYTES>>>(atoms, adj, sel, emb,
                                           b1, b2, wp, bp, out);
}

// round 5
// speedup vs baseline: 2.0736x; 1.8179x over previous
#include <cuda_runtime.h>
#include <cuda_bf16.h>
#include <cstdint>

// ============================================================================
// PathwayPredictor, mma.sync bf16-split, 2 molecules/CTA, 256 threads.
// GEMM1: X(embed, direct-LDG frags) @ W1^T   [K=80]
// GEMM2: A(split,smem) @ H1(smem)            [K=64]
// GEMM3: D2(in-register chain!) @ W2^T       [K=80]
// pool collapse: y = colsum(A) @ relu(D3+b2); tiny head.
// ============================================================================

#define SWW 44   // W row stride, u32 words (88 bf16)
#define SHW 36   // H / Asplit row stride, u32 words (72 bf16)

// smem float indices
#define B1I 0       // b1 padded [72]
#define B2I 72      // b2 padded [72]
#define BPI 144     // bp [11] (pad 16)
#define CSI 160     // csum [128]  (mol-major)
#define PLI 288     // pool partials [8][72]
#define YI  864     // y [2][72]
#define WPI 1008    // wp [847]
#define ATI 1856    // atoms int [128]
// byte offsets
#define OFF_H 7936      // 2 x (72x72 hi + 72x72 lo) b16 = 41472 ; ALIASES A fp32 staging [2][64][65]
#define OFF_W 49408     // 72x88 hi + lo b16 = 25344 (W1 then W2)
#define OFF_A 74752     // 2 x (64x72 hi + lo) b16 = 36864
#define SMEM_BYTES 111616
#define WTILE 12672
#define HTILE 20736
#define ATILE 18432

__device__ __align__(16) unsigned char g_wt[2][2][WTILE];  // [layer][hi/lo]

// ---------------- helpers ----------------
__device__ __forceinline__ void split2(float v, uint16_t& h, uint16_t& l) {
    __nv_bfloat16 bh = __float2bfloat16(v);
    h = *reinterpret_cast<uint16_t*>(&bh);
    __nv_bfloat16 bl = __float2bfloat16(v - __bfloat162float(bh));
    l = *reinterpret_cast<uint16_t*>(&bl);
}
__device__ __forceinline__ void split2w(float a, float b, uint32_t& hw, uint32_t& lw) {
    uint16_t h0, l0, h1, l1;
    split2(a, h0, l0); split2(b, h1, l1);
    hw = (uint32_t)h0 | ((uint32_t)h1 << 16);
    lw = (uint32_t)l0 | ((uint32_t)l1 << 16);
}
__device__ __forceinline__ void mma16816(float c[4],
    uint32_t a0, uint32_t a1, uint32_t a2, uint32_t a3, uint32_t b0, uint32_t b1)
{
    asm volatile(
        "mma.sync.aligned.m16n8k16.row.col.f32.bf16.bf16.f32 "
        "{%0,%1,%2,%3},{%4,%5,%6,%7},{%8,%9},{%0,%1,%2,%3};"
        : "+f"(c[0]), "+f"(c[1]), "+f"(c[2]), "+f"(c[3])
        : "r"(a0), "r"(a1), "r"(a2), "r"(a3), "r"(b0), "r"(b1));
}
// 9 n-tiles: load B hi/lo frags, 3-term MMA into C.
__device__ __forceinline__ void mma3_n9(
    const uint32_t* __restrict__ Bhi, const uint32_t* __restrict__ Blo,
    int rbase, int sb, int q,
    uint32_t ah0, uint32_t ah1, uint32_t ah2, uint32_t ah3,
    uint32_t al0, uint32_t al1, uint32_t al2, uint32_t al3,
    float C[9][4])
{
    #pragma unroll
    for (int n = 0; n < 9; n++) {
        const int rb = (n * 8 + q) * sb + rbase;
        uint32_t bh0 = Bhi[rb], bh1 = Bhi[rb + 4];
        uint32_t bl0 = Blo[rb], bl1 = Blo[rb + 4];
        mma16816(C[n], ah0, ah1, ah2, ah3, bh0, bh1);
        mma16816(C[n], ah0, ah1, ah2, ah3, bl0, bl1);
        mma16816(C[n], al0, al1, al2, al3, bh0, bh1);
    }
}

// ---------------- weight prep: W^T split tiles [72 n][88 k] hi/lo ----------------
__global__ void prep_w(const float* __restrict__ w1, const float* __restrict__ w2) {
    int idx = blockIdx.x * 128 + threadIdx.x;
    if (idx >= 2 * 72 * 88) return;
    int l = idx / (72 * 88);
    int r = idx % (72 * 88);
    int n = r / 88, k = r % 88;
    const float* w = l ? w2 : w1;
    float v = (n < 70 && k < 70) ? w[k * 70 + n] : 0.f;
    uint16_t h, lo; split2(v, h, lo);
    *(uint16_t*)(g_wt[l][0] + r * 2) = h;
    *(uint16_t*)(g_wt[l][1] + r * 2) = lo;
}

// ---------------- main kernel ----------------
__global__ __launch_bounds__(256, 2)
void pathway_mma2(const int* __restrict__ atoms, const float* __restrict__ adj,
                  const float* __restrict__ sel, const float* __restrict__ emb,
                  const float* __restrict__ b1, const float* __restrict__ b2,
                  const float* __restrict__ wp, const float* __restrict__ bp,
                  float* __restrict__ out)
{
    extern __shared__ __align__(16) unsigned char sm[];
    float* smf = (float*)sm;
    int*   smi = (int*)sm;
    const int t = threadIdx.x, lane = t & 31, wid = t >> 5;
    const int bid = blockIdx.x;
    const int q = lane >> 2, qp = lane & 3;
    const int mol = wid >> 2;                 // molecule 0/1
    const int mrow = wid * 16;                // global row 0..112
    const int mloc = mrow & 63;               // row within molecule

    uint32_t* Whi = (uint32_t*)(sm + OFF_W);  uint32_t* Wlo = Whi + 72 * SWW;
    uint32_t* Hhi = (uint32_t*)(sm + OFF_H + mol * HTILE);
    uint32_t* Hlo = Hhi + 72 * SHW;
    uint16_t* H16h = (uint16_t*)(sm + OFF_H + mol * HTILE);
    uint16_t* H16l = H16h + 72 * 72;
    uint32_t* Ahi = (uint32_t*)(sm + OFF_A + mol * ATILE);
    uint32_t* Alo = Ahi + 64 * SHW;
    float* stg = smf + OFF_H / 4;             // [2][64][65] fp32, aliases H

    // ================= phase 0: loads =================
    {   // adjacency fp32 -> staging, coalesced
        const float* Ab = adj + (size_t)bid * 8192;
        #pragma unroll
        for (int i = t; i < 8192; i += 256) {
            int m2 = i >> 12, ii = i & 4095;
            stg[m2 * 4160 + (ii >> 6) * 65 + (ii & 63)] = Ab[i];
        }
    }
    {   // W1 split tiles
        const uint4* gw = (const uint4*)g_wt[0][0];
        uint4* sw = (uint4*)(sm + OFF_W);
        #pragma unroll
        for (int i = t; i < 2 * WTILE / 16; i += 256) sw[i] = gw[i];
    }
    if (t < 128) smi[ATI + t] = atoms[(size_t)bid * 128 + t];
    if (t < 72) { smf[B1I + t] = (t < 70) ? b1[t] : 0.f;
                  smf[B2I + t] = (t < 70) ? b2[t] : 0.f; }
    if (t < 11) smf[BPI + t] = bp[t];
    for (int i = t; i < 847; i += 256) smf[WPI + i] = wp[i];
    __syncthreads();

    // ================= phase 1: colsum + A split =================
    if (t < 128) {
        const float* cb = stg + (t >> 6) * 4160 + (t & 63);
        float s = 0.f;
        #pragma unroll 8
        for (int n = 0; n < 64; n++) s += cb[n * 65];
        smf[CSI + t] = s;
    }
    {   // split A rows: thread -> (molA, row n, half)
        const int molA = t >> 7, n = (t >> 1) & 63, half = t & 1;
        const float* ar = stg + molA * 4160 + n * 65 + half * 32;
        uint32_t* ah = (uint32_t*)(sm + OFF_A + molA * ATILE) + n * SHW + half * 16;
        uint32_t* al = ah + 64 * SHW;
        #pragma unroll
        for (int j = 0; j < 16; j++) {
            uint32_t hw, lw; split2w(ar[2 * j], ar[2 * j + 1], hw, lw);
            ah[j] = hw; al[j] = lw;
        }
    }
    __syncthreads();   // staging dead from here (H may be written)

    float C[9][4];
    #pragma unroll
    for (int n = 0; n < 9; n++)
        #pragma unroll
        for (int i = 0; i < 4; i++) C[n][i] = 0.f;

    // ================= GEMM1: D1 = X @ W1^T  (K=80, X frags via LDG) ========
    {
        const int a0i = smi[ATI + mrow + q];
        const int a1i = smi[ATI + mrow + q + 8];
        const float2* e0 = (const float2*)(emb + (size_t)a0i * 70);
        const float2* e1 = (const float2*)(emb + (size_t)a1i * 70);
        float2 v[5][4];
        const float2 z2 = make_float2(0.f, 0.f);
        #pragma unroll
        for (int ks = 0; ks < 5; ks++) {
            const int k0 = 16 * ks + 2 * qp, k1 = k0 + 8;
            v[ks][0] = (k0 < 70) ? e0[k0 >> 1] : z2;
            v[ks][1] = (k0 < 70) ? e1[k0 >> 1] : z2;
            v[ks][2] = (k1 < 70) ? e0[k1 >> 1] : z2;
            v[ks][3] = (k1 < 70) ? e1[k1 >> 1] : z2;
        }
        #pragma unroll
        for (int ks = 0; ks < 5; ks++) {
            uint32_t ah0, al0, ah1, al1, ah2, al2, ah3, al3;
            split2w(v[ks][0].x, v[ks][0].y, ah0, al0);
            split2w(v[ks][1].x, v[ks][1].y, ah1, al1);
            split2w(v[ks][2].x, v[ks][2].y, ah2, al2);
            split2w(v[ks][3].x, v[ks][3].y, ah3, al3);
            mma3_n9(Whi, Wlo, ks * 8 + qp, SWW, q,
                    ah0, ah1, ah2, ah3, al0, al1, al2, al3, C);
        }
    }

    // ---- epi1: H1 = relu(D1+b1) -> H^T hi/lo (per-mol region) ----
    {
        const int r0 = mloc + q, r1 = r0 + 8;
        #pragma unroll
        for (int n = 0; n < 9; n++) {
            const int d0 = n * 8 + qp * 2;
            float h00 = fmaxf(C[n][0] + smf[B1I + d0], 0.f);
            float h01 = fmaxf(C[n][1] + smf[B1I + d0 + 1], 0.f);
            float h10 = fmaxf(C[n][2] + smf[B1I + d0], 0.f);
            float h11 = fmaxf(C[n][3] + smf[B1I + d0 + 1], 0.f);
            uint16_t hh, hl;
            split2(h00, hh, hl); H16h[d0 * 72 + r0] = hh;       H16l[d0 * 72 + r0] = hl;
            split2(h01, hh, hl); H16h[(d0 + 1) * 72 + r0] = hh; H16l[(d0 + 1) * 72 + r0] = hl;
            split2(h10, hh, hl); H16h[d0 * 72 + r1] = hh;       H16l[d0 * 72 + r1] = hl;
            split2(h11, hh, hl); H16h[(d0 + 1) * 72 + r1] = hh; H16l[(d0 + 1) * 72 + r1] = hl;
        }
    }
    __syncthreads();   // H ready everywhere; W1 fully consumed

    {   // W2 split tiles over W1
        const uint4* gw = (const uint4*)g_wt[1][0];
        uint4* sw = (uint4*)(sm + OFF_W);
        #pragma unroll
        for (int i = t; i < 2 * WTILE / 16; i += 256) sw[i] = gw[i];
    }

    // ================= GEMM2: D2 = A @ H1  (K=64) =================
    #pragma unroll
    for (int n = 0; n < 9; n++)
        #pragma unroll
        for (int i = 0; i < 4; i++) C[n][i] = 0.f;
    #pragma unroll
    for (int ks = 0; ks < 4; ks++) {
        const int ra = (mloc + q) * SHW + ks * 8 + qp;
        uint32_t ah0 = Ahi[ra],     ah1 = Ahi[ra + 8 * SHW];
        uint32_t ah2 = Ahi[ra + 4], ah3 = Ahi[ra + 8 * SHW + 4];
        uint32_t al0 = Alo[ra],     al1 = Alo[ra + 8 * SHW];
        uint32_t al2 = Alo[ra + 4], al3 = Alo[ra + 8 * SHW + 4];
        mma3_n9(Hhi, Hlo, ks * 8 + qp, SHW, q,
                ah0, ah1, ah2, ah3, al0, al1, al2, al3, C);
    }
    __syncthreads();   // W2 stores complete

    // ================= GEMM3: D3 = D2 @ W2^T (A-frags chained in-register) ==
    float C3[9][4];
    #pragma unroll
    for (int n = 0; n < 9; n++)
        #pragma unroll
        for (int i = 0; i < 4; i++) C3[n][i] = 0.f;
    #pragma unroll
    for (int ks = 0; ks < 5; ks++) {
        uint32_t ah0, al0, ah1, al1, ah2, al2, ah3, al3;
        split2w(C[2 * ks][0], C[2 * ks][1], ah0, al0);
        split2w(C[2 * ks][2], C[2 * ks][3], ah1, al1);
        if (ks < 4) {
            split2w(C[2 * ks + 1][0], C[2 * ks + 1][1], ah2, al2);
            split2w(C[2 * ks + 1][2], C[2 * ks + 1][3], ah3, al3);
        } else { ah2 = al2 = ah3 = al3 = 0u; }
        mma3_n9(Whi, Wlo, ks * 8 + qp, SWW, q,
                ah0, ah1, ah2, ah3, al0, al1, al2, al3, C3);
    }

    // ---- epi3: pool partials y[d] += csum[r] * relu(D3[r][d]+b2[d]) ----
    {
        const float cs0 = smf[CSI + mrow + q];
        const float cs1 = smf[CSI + mrow + q + 8];
        #pragma unroll
        for (int n = 0; n < 9; n++) {
            #pragma unroll
            for (int j = 0; j < 2; j++) {
                const int d = n * 8 + qp * 2 + j;
                float v = cs0 * fmaxf(C3[n][j] + smf[B2I + d], 0.f)
                        + cs1 * fmaxf(C3[n][2 + j] + smf[B2I + d], 0.f);
                v += __shfl_xor_sync(0xFFFFFFFFu, v, 4);
                v += __shfl_xor_sync(0xFFFFFFFFu, v, 8);
                v += __shfl_xor_sync(0xFFFFFFFFu, v, 16);
                if (q == 0) smf[PLI + wid * 72 + d] = v;
            }
        }
    }
    __syncthreads();

    // reduce 4 warps per molecule
    if (t < 144) {
        const int mY = t / 72, d = t - mY * 72;
        float y = smf[PLI + (mY * 4 + 0) * 72 + d] + smf[PLI + (mY * 4 + 1) * 72 + d]
                + smf[PLI + (mY * 4 + 2) * 72 + d] + smf[PLI + (mY * 4 + 3) * 72 + d];
        smf[YI + t] = y;
    }
    __syncthreads();

    // head
    if (t < 22) {
        const int mH = t / 11, c = t - mH * 11;
        float s = smf[BPI + c];
        #pragma unroll 7
        for (int d = 0; d < 70; d++)
            s += smf[YI + mH * 72 + d] * smf[WPI + d * 11 + c];
        const float* sv = sel + (size_t)(2 * bid + mH) * 7;
        #pragma unroll
        for (int e = 0; e < 7; e++)
            s += __ldg(&sv[e]) * smf[WPI + (70 + e) * 11 + c];
        out[(size_t)(2 * bid + mH) * 11 + c] = s;
    }
}

extern "C" void kernel_launch(void* const* d_in, const int* in_sizes, int n_in,
                              void* d_out, int out_size)
{
    const int*   atoms = (const int*)  d_in[0];
    const float* adj   = (const float*)d_in[1];
    const float* sel   = (const float*)d_in[2];
    const float* emb   = (const float*)d_in[3];
    const float* w1    = (const float*)d_in[4];
    const float* b1    = (const float*)d_in[5];
    const float* w2    = (const float*)d_in[6];
    const float* b2    = (const float*)d_in[7];
    const float* wp    = (const float*)d_in[8];
    const float* bp    = (const float*)d_in[9];
    float* out = (float*)d_out;

    prep_w<<<(2 * 72 * 88 + 127) / 128, 128>>>(w1, w2);

    cudaFuncSetAttribute(pathway_mma2,
                         cudaFuncAttributeMaxDynamicSharedMemorySize, SMEM_BYTES);
    pathway_mma2<<<4096, 256, SMEM_BYTES>>>(atoms, adj, sel, emb,
                                            b1, b2, wp, bp, out);
}